// round 15
// baseline (speedup 1.0000x reference)
#include <cuda_runtime.h>
#include <cstdint>
#include <cstddef>

#define T_STEPS 256
#define BATCH   2048
#define M_TOTAL (T_STEPS * BATCH)   // 524288 rows
#define AP      132                 // padded smem row (floats), conflict-free fragments

// zx scratch, layout [t][b][p] (p = g*16+n), +2 timesteps prefetch padding
__device__ float g_zx[((size_t)M_TOTAL + 3 * BATCH) * 64];

__device__ __forceinline__ uint32_t tf32_of(float x) {
    float y; asm("cvt.rna.tf32.f32 %0, %1;" : "=f"(y) : "f"(x));
    return __float_as_uint(y);
}
__device__ __forceinline__ float4 tf32_4(float4 v) {
    v.x = __uint_as_float(tf32_of(v.x)); v.y = __uint_as_float(tf32_of(v.y));
    v.z = __uint_as_float(tf32_of(v.z)); v.w = __uint_as_float(tf32_of(v.w));
    return v;
}
__device__ __forceinline__ float ex2a(float x) {
    float y; asm("ex2.approx.ftz.f32 %0, %1;" : "=f"(y) : "f"(x)); return y;
}
__device__ __forceinline__ float rcpa(float x) {
    float y; asm("rcp.approx.ftz.f32 %0, %1;" : "=f"(y) : "f"(x)); return y;
}
__device__ __forceinline__ float tanh_f(float x) {
    return fmaf(2.f, rcpa(1.f + ex2a(-2.88539008f * x)), -1.f);
}

__device__ __forceinline__ void mma_tf32(float c[4], uint32_t a0, uint32_t a1,
                                         uint32_t a2, uint32_t a3,
                                         uint32_t b0, uint32_t b1) {
    asm volatile(
        "mma.sync.aligned.m16n8k8.row.col.f32.tf32.tf32.f32 "
        "{%0,%1,%2,%3}, {%4,%5,%6,%7}, {%8,%9}, {%0,%1,%2,%3};"
        : "+f"(c[0]), "+f"(c[1]), "+f"(c[2]), "+f"(c[3])
        : "r"(a0), "r"(a1), "r"(a2), "r"(a3), "r"(b0), "r"(b1));
}

// ---------------------------------------------------------------------------
// Phase 1: zx = X*W^T + bias + theta via mma.sync tf32 m16n8k8. (unchanged)
// ---------------------------------------------------------------------------
__global__ __launch_bounds__(256, 2)
void qlstm_phase1(const float* __restrict__ X, const float* __restrict__ W,
                  const float* __restrict__ bias, const float* __restrict__ theta)
{
    extern __shared__ float sm[];
    float* Ash = sm;                 // [128][AP]
    float* Wsh = sm + 128 * AP;      // [64][AP]
    float* bt  = Wsh + 64 * AP;      // [64]
    const int tid = threadIdx.x;

    const float4* Xg = reinterpret_cast<const float4*>(X + (size_t)blockIdx.x * (128 * 128));
#pragma unroll
    for (int it = 0; it < 16; ++it) {
        int i = tid + it * 256;
        int row = i >> 5, c4 = i & 31;
        *reinterpret_cast<float4*>(&Ash[row * AP + c4 * 4]) = tf32_4(Xg[i]);
    }
#pragma unroll
    for (int it = 0; it < 8; ++it) {
        int i = tid + it * 256;
        int p = i >> 5, c4 = i & 31;
        float4 v = *reinterpret_cast<const float4*>(W + (size_t)p * 144 + c4 * 4);
        *reinterpret_cast<float4*>(&Wsh[p * AP + c4 * 4]) = tf32_4(v);
    }
    if (tid < 64) bt[tid] = bias[tid] + theta[tid];
    __syncthreads();

    const int w = tid >> 5, lane = tid & 31;
    const int g = lane >> 2, t4 = lane & 3;

    float acc[8][4];
#pragma unroll
    for (int nt = 0; nt < 8; ++nt)
#pragma unroll
        for (int j = 0; j < 4; ++j) acc[nt][j] = 0.f;

    const float* abase = Ash + (16 * w + g) * AP + t4;
    const float* bbase = Wsh + g * AP + t4;

#pragma unroll
    for (int k0 = 0; k0 < 16; ++k0) {
        const float* ap = abase + k0 * 8;
        uint32_t a0 = __float_as_uint(ap[0]);
        uint32_t a1 = __float_as_uint(ap[8 * AP]);
        uint32_t a2 = __float_as_uint(ap[4]);
        uint32_t a3 = __float_as_uint(ap[8 * AP + 4]);
        const float* bp = bbase + k0 * 8;
#pragma unroll
        for (int nt = 0; nt < 8; ++nt) {
            uint32_t b0 = __float_as_uint(bp[nt * 8 * AP]);
            uint32_t b1 = __float_as_uint(bp[nt * 8 * AP + 4]);
            mma_tf32(acc[nt], a0, a1, a2, a3, b0, b1);
        }
    }
    __syncthreads();

    float* epi = sm;   // [128][66]
    {
        const int r0 = 16 * w + g, r1 = r0 + 8;
#pragma unroll
        for (int nt = 0; nt < 8; ++nt) {
            *reinterpret_cast<float2*>(&epi[r0 * 66 + nt * 8 + 2 * t4]) =
                make_float2(acc[nt][0], acc[nt][1]);
            *reinterpret_cast<float2*>(&epi[r1 * 66 + nt * 8 + 2 * t4]) =
                make_float2(acc[nt][2], acc[nt][3]);
        }
    }
    __syncthreads();
    {
        float* og = g_zx + (size_t)blockIdx.x * (128 * 64);
#pragma unroll
        for (int it = 0; it < 32; ++it) {
            int i = tid + it * 256;
            int m = i >> 6, c = i & 63;
            og[i] = epi[m * 66 + c] + bt[c];
        }
    }
}

// ---------------------------------------------------------------------------
// Phase 2: 4 batch elements per warp = 2 independent "pairs" (unroll-and-jam).
// Within a pair: lane = e*16 + g*4 + k owns gate g, n in {4k..4k+3}.
// wh registers are shared between pairs; chains interleave for ILP.
// ---------------------------------------------------------------------------
__global__ __launch_bounds__(32)
void qlstm_phase2(const float* __restrict__ W, float* __restrict__ out)
{
    __shared__ float hbuf[2][2][16];     // [pair][e][n]
    __shared__ float qbuf[2][2][4][16];  // [pair][e][gate][n]

    const int lane = threadIdx.x & 31;
    const int e    = lane >> 4;
    const int lq   = lane & 15;
    const int g    = lq >> 2;
    const int k    = lq & 3;
    const int b0   = 4 * blockIdx.x + e;   // pair 0 element
    const int b1   = b0 + 2;               // pair 1 element

    // recurrent weights (shared across both pairs)
    float wh[4][16];
#pragma unroll
    for (int i = 0; i < 4; ++i)
#pragma unroll
        for (int j = 0; j < 16; ++j)
            wh[i][j] = W[(size_t)(g * 16 + 4 * k + i) * 144 + 128 + j];

    const float m2 = (g == 2) ? 2.f : 1.f;
    const float a0 = (g == 2) ? -1.f : 0.f;
    const float km = -1.44269504f * m2;

    float c[2][4];
#pragma unroll
    for (int P = 0; P < 2; ++P)
#pragma unroll
        for (int i = 0; i < 4; ++i) c[P][i] = 0.f;

    hbuf[0][e][lq] = 0.f;
    hbuf[1][e][lq] = 0.f;
    __syncwarp();

    const size_t S = (size_t)BATCH * 16;   // per-t stride in float4
    const float4* zp0 = reinterpret_cast<const float4*>(g_zx) + (size_t)b0 * 16 + lq;
    const float4* zp1 = reinterpret_cast<const float4*>(g_zx) + (size_t)b1 * 16 + lq;
    float4 f0[2] = {__ldg(zp0), __ldg(zp1)};
    float4 f1[2] = {__ldg(zp0 + S), __ldg(zp1 + S)};
    const float4* zpf0 = zp0 + 2 * S;
    const float4* zpf1 = zp1 + 2 * S;

    float* outp0 = out + (size_t)b0 * 16 + 4 * k;
    float* outp1 = out + (size_t)b1 * 16 + 4 * k;

    for (int t = 0; t < T_STEPS; ++t) {
        // gather h for both pairs (broadcast LDS)
        float hh[2][16];
#pragma unroll
        for (int P = 0; P < 2; ++P) {
            const float4* hb = reinterpret_cast<const float4*>(hbuf[P][e]);
            float4 x0 = hb[0], x1 = hb[1], x2 = hb[2], x3 = hb[3];
            hh[P][0] = x0.x; hh[P][1] = x0.y; hh[P][2] = x0.z; hh[P][3] = x0.w;
            hh[P][4] = x1.x; hh[P][5] = x1.y; hh[P][6] = x1.z; hh[P][7] = x1.w;
            hh[P][8] = x2.x; hh[P][9] = x2.y; hh[P][10] = x2.z; hh[P][11] = x2.w;
            hh[P][12] = x3.x; hh[P][13] = x3.y; hh[P][14] = x3.z; hh[P][15] = x3.w;
        }

        float z[2][4], s[2][4];
        z[0][0] = f0[0].x; z[0][1] = f0[0].y; z[0][2] = f0[0].z; z[0][3] = f0[0].w;
        z[1][0] = f0[1].x; z[1][1] = f0[1].y; z[1][2] = f0[1].z; z[1][3] = f0[1].w;
        f0[0] = f1[0]; f0[1] = f1[1];
        f1[0] = __ldg(zpf0); zpf0 += S;
        f1[1] = __ldg(zpf1); zpf1 += S;
#pragma unroll
        for (int P = 0; P < 2; ++P)
#pragma unroll
            for (int i = 0; i < 4; ++i) s[P][i] = 0.f;

        // z[P][i] += sum_j wh[i][j]*hh[P][j]  (pairs interleaved for ILP)
#pragma unroll
        for (int j = 0; j < 8; ++j) {
#pragma unroll
            for (int P = 0; P < 2; ++P) {
                z[P][0] = fmaf(wh[0][j], hh[P][j], z[P][0]);
                s[P][0] = fmaf(wh[0][j + 8], hh[P][j + 8], s[P][0]);
                z[P][1] = fmaf(wh[1][j], hh[P][j], z[P][1]);
                s[P][1] = fmaf(wh[1][j + 8], hh[P][j + 8], s[P][1]);
                z[P][2] = fmaf(wh[2][j], hh[P][j], z[P][2]);
                s[P][2] = fmaf(wh[2][j + 8], hh[P][j + 8], s[P][2]);
                z[P][3] = fmaf(wh[3][j], hh[P][j], z[P][3]);
                s[P][3] = fmaf(wh[3][j + 8], hh[P][j + 8], s[P][3]);
            }
        }
#pragma unroll
        for (int P = 0; P < 2; ++P)
#pragma unroll
            for (int i = 0; i < 4; ++i) z[P][i] += s[P][i];

        // in-lane prefix products of cos
        float p[2][4];
#pragma unroll
        for (int P = 0; P < 2; ++P) {
            p[P][0] = __cosf(z[P][0]);
            p[P][1] = p[P][0] * __cosf(z[P][1]);
            p[P][2] = p[P][1] * __cosf(z[P][2]);
            p[P][3] = p[P][2] * __cosf(z[P][3]);
        }

        // cross-lane exclusive prefix of lane totals (width-4 = one gate), pairs interleaved
        float inc0 = p[0][3], inc1 = p[1][3];
        {
            float v0 = __shfl_up_sync(0xffffffffu, inc0, 1, 4);
            float v1 = __shfl_up_sync(0xffffffffu, inc1, 1, 4);
            inc0 *= (k >= 1) ? v0 : 1.f;
            inc1 *= (k >= 1) ? v1 : 1.f;
            v0 = __shfl_up_sync(0xffffffffu, inc0, 2, 4);
            v1 = __shfl_up_sync(0xffffffffu, inc1, 2, 4);
            inc0 *= (k >= 2) ? v0 : 1.f;
            inc1 *= (k >= 2) ? v1 : 1.f;
        }
        float ex0 = __shfl_up_sync(0xffffffffu, inc0, 1, 4);
        float ex1 = __shfl_up_sync(0xffffffffu, inc1, 1, 4);
        ex0 = (k >= 1) ? ex0 : 1.f;
        ex1 = (k >= 1) ? ex1 : 1.f;

        // activation (sigmoid, or tanh for gate 2, branchless), then exchange
        float u[2][4];
#pragma unroll
        for (int i = 0; i < 4; ++i) {
            float q0 = p[0][i] * ex0;
            float q1 = p[1][i] * ex1;
            u[0][i] = fmaf(rcpa(1.f + ex2a(km * q0)), m2, a0);
            u[1][i] = fmaf(rcpa(1.f + ex2a(km * q1)), m2, a0);
        }
        *reinterpret_cast<float4*>(&qbuf[0][e][g][4 * k]) =
            make_float4(u[0][0], u[0][1], u[0][2], u[0][3]);
        *reinterpret_cast<float4*>(&qbuf[1][e][g][4 * k]) =
            make_float4(u[1][0], u[1][1], u[1][2], u[1][3]);
        __syncwarp();

        if (g == 0) {
#pragma unroll
            for (int P = 0; P < 2; ++P) {
                float4 fi = *reinterpret_cast<const float4*>(&qbuf[P][e][1][4 * k]);
                float4 gu = *reinterpret_cast<const float4*>(&qbuf[P][e][2][4 * k]);
                float4 oo = *reinterpret_cast<const float4*>(&qbuf[P][e][3][4 * k]);
                c[P][0] = fmaf(u[P][0], c[P][0], fi.x * gu.x);
                c[P][1] = fmaf(u[P][1], c[P][1], fi.y * gu.y);
                c[P][2] = fmaf(u[P][2], c[P][2], fi.z * gu.z);
                c[P][3] = fmaf(u[P][3], c[P][3], fi.w * gu.w);
                float hn0 = oo.x * tanh_f(c[P][0]);
                float hn1 = oo.y * tanh_f(c[P][1]);
                float hn2 = oo.z * tanh_f(c[P][2]);
                float hn3 = oo.w * tanh_f(c[P][3]);
                float4 hv = make_float4(hn0, hn1, hn2, hn3);
                *reinterpret_cast<float4*>(&hbuf[P][e][4 * k]) = hv;
                float* op = (P == 0) ? outp0 : outp1;
                *reinterpret_cast<float4*>(op + (size_t)t * (BATCH * 16)) = hv;
            }
        }
        __syncwarp();
    }

    if (g == 0) {
        const size_t hx = (size_t)T_STEPS * BATCH * 16;
#pragma unroll
        for (int P = 0; P < 2; ++P) {
            const int b = (P == 0) ? b0 : b1;
            *reinterpret_cast<float4*>(&out[hx + (size_t)b * 16 + 4 * k]) =
                *reinterpret_cast<const float4*>(&hbuf[P][e][4 * k]);
            *reinterpret_cast<float4*>(&out[hx + (size_t)BATCH * 16 + (size_t)b * 16 + 4 * k]) =
                make_float4(c[P][0], c[P][1], c[P][2], c[P][3]);
        }
    }
}

extern "C" void kernel_launch(void* const* d_in, const int* in_sizes, int n_in,
                              void* d_out, int out_size)
{
    const float* X  = (const float*)d_in[0];
    const float* W  = (const float*)d_in[1];
    const float* bb = (const float*)d_in[2];
    const float* th = (const float*)d_in[3];
    float* out = (float*)d_out;

    const int smem = (128 * AP + 64 * AP + 64) * (int)sizeof(float);  // ~101.6 KB
    cudaFuncSetAttribute(qlstm_phase1, cudaFuncAttributeMaxDynamicSharedMemorySize, smem);
    qlstm_phase1<<<M_TOTAL / 128, 256, smem>>>(X, W, bb, th);
    qlstm_phase2<<<BATCH / 4, 32>>>(W, out);
}